// round 14
// baseline (speedup 1.0000x reference)
#include <cuda_runtime.h>
#include <cuda_bf16.h>
#include <cstdint>

#define N_NODES 50000
#define N_EDGES 600000
#define D 128
#define DE 32

// ---------------------------------------------------------------------------
// Scratch (static device globals — no runtime allocation allowed)
// ---------------------------------------------------------------------------
__device__ int   g_src[N_EDGES];
__device__ int   g_dst[N_EDGES];
__device__ int   g_cnt[N_NODES + 1];
__device__ int   g_off[N_NODES + 1];
__device__ int   g_sdst[N_EDGES];
__device__ int   g_ssrc[N_EDGES];
__device__ int   g_sperm[N_EDGES];
__device__ float g_bufA[N_NODES * D];
__device__ float g_bufB[N_NODES * D];
__device__ float g_bufC[N_NODES * D];
__device__ int   g_is64;
// node-GEMM weights: [6][128x128 bf16] in B-operand layout (stride 256B, XOR swizzle)
__device__ __nv_bfloat16 g_whi[6][D * D];
__device__ __nv_bfloat16 g_wlo[6][D * D];
// edge weights: [2 layers][128 n-rows x 80B stride] hi/lo planes (5120 bf16 each)
__device__ __nv_bfloat16 g_wehi[2][5120];
__device__ __nv_bfloat16 g_welo[2][5120];

// ---------------------------------------------------------------------------
// helpers
// ---------------------------------------------------------------------------
__device__ __forceinline__ uint32_t smem_to_u32(const void* p) {
    uint32_t a;
    asm("{ .reg .u64 t; cvta.to.shared.u64 t, %1; cvt.u32.u64 %0, t; }" : "=r"(a) : "l"(p));
    return a;
}

__device__ __host__ __forceinline__ uint32_t sw_off(int row, int col) {
    return (uint32_t)row * 256u + (uint32_t)(((col >> 3) ^ (row & 7)) << 4)
         + (uint32_t)(col & 7) * 2u;
}
__device__ __host__ __forceinline__ uint32_t esw_off(int row, int col) {
    return (uint32_t)row * 80u + (uint32_t)((col >> 3) << 4) + (uint32_t)(col & 7) * 2u;
}

__device__ __forceinline__ void ldsm4(uint32_t* r, uint32_t addr) {
    asm volatile("ldmatrix.sync.aligned.m8n8.x4.shared.b16 {%0,%1,%2,%3}, [%4];"
                 : "=r"(r[0]), "=r"(r[1]), "=r"(r[2]), "=r"(r[3]) : "r"(addr));
}

__device__ __forceinline__ void mma_bf16(float* d, const uint32_t* a, const uint32_t* b) {
    asm volatile("mma.sync.aligned.m16n8k16.row.col.f32.bf16.bf16.f32 "
                 "{%0,%1,%2,%3}, {%4,%5,%6,%7}, {%8,%9}, {%0,%1,%2,%3};"
                 : "+f"(d[0]), "+f"(d[1]), "+f"(d[2]), "+f"(d[3])
                 : "r"(a[0]), "r"(a[1]), "r"(a[2]), "r"(a[3]), "r"(b[0]), "r"(b[1]));
}

__device__ __forceinline__ void split_pack(float4 v, uint2& hi, uint2& lo) {
    __nv_bfloat16 hx = __float2bfloat16(v.x), hy = __float2bfloat16(v.y);
    __nv_bfloat16 hz = __float2bfloat16(v.z), hw = __float2bfloat16(v.w);
    __nv_bfloat16 lx = __float2bfloat16(v.x - __bfloat162float(hx));
    __nv_bfloat16 ly = __float2bfloat16(v.y - __bfloat162float(hy));
    __nv_bfloat16 lz = __float2bfloat16(v.z - __bfloat162float(hz));
    __nv_bfloat16 lw = __float2bfloat16(v.w - __bfloat162float(hw));
    hi.x = ((uint32_t)__bfloat16_as_ushort(hy) << 16) | __bfloat16_as_ushort(hx);
    hi.y = ((uint32_t)__bfloat16_as_ushort(hw) << 16) | __bfloat16_as_ushort(hz);
    lo.x = ((uint32_t)__bfloat16_as_ushort(ly) << 16) | __bfloat16_as_ushort(lx);
    lo.y = ((uint32_t)__bfloat16_as_ushort(lw) << 16) | __bfloat16_as_ushort(lz);
}

// ---------------------------------------------------------------------------
// edge_index dtype detection / conversion / copy
// ---------------------------------------------------------------------------
__global__ void detect_kernel(const int* __restrict__ p, int n_words) {
    if (threadIdx.x == 0 && blockIdx.x == 0) {
        int all0 = 1;
        int lim = n_words / 2 < 64 ? n_words / 2 : 64;
        for (int i = 0; i < lim; i++) {
            if (p[2 * i + 1] != 0) { all0 = 0; break; }
        }
        g_is64 = all0;
    }
}

__global__ void convert_kernel(const void* __restrict__ eidx) {
    int e = blockIdx.x * blockDim.x + threadIdx.x;
    if (e >= N_EDGES) return;
    if (g_is64) {
        const long long* p = (const long long*)eidx;
        g_src[e] = (int)p[e];
        g_dst[e] = (int)p[N_EDGES + e];
    } else {
        const int* p = (const int*)eidx;
        g_src[e] = p[e];
        g_dst[e] = p[N_EDGES + e];
    }
}

__global__ void copy_kernel(const float4* __restrict__ src, float4* __restrict__ dst, int n4) {
    int i = blockIdx.x * blockDim.x + threadIdx.x;
    if (i < n4) dst[i] = src[i];
}

// ---------------------------------------------------------------------------
// dst counting sort: zero + hist, block scan, scatter
// ---------------------------------------------------------------------------
__global__ void zero_kernel(int* __restrict__ p, int n) {
    int i = blockIdx.x * blockDim.x + threadIdx.x;
    if (i < n) p[i] = 0;
}

__global__ void hist_kernel() {
    int e = blockIdx.x * blockDim.x + threadIdx.x;
    if (e < N_EDGES) atomicAdd(&g_cnt[g_dst[e]], 1);
}

__global__ void __launch_bounds__(1024) scan_kernel() {
    __shared__ int part[1024];
    const int CH = (N_NODES + 1023) / 1024;   // 49
    int t = threadIdx.x;
    int base = t * CH;
    int s = 0;
    for (int i = 0; i < CH; i++) {
        int j = base + i;
        if (j < N_NODES) s += g_cnt[j];
    }
    part[t] = s;
    __syncthreads();
    // Hillis-Steele inclusive scan
    for (int d = 1; d < 1024; d <<= 1) {
        int v = (t >= d) ? part[t - d] : 0;
        __syncthreads();
        part[t] += v;
        __syncthreads();
    }
    int pre = (t == 0) ? 0 : part[t - 1];
    for (int i = 0; i < CH; i++) {
        int j = base + i;
        if (j < N_NODES) {
            int c = g_cnt[j];
            g_off[j] = pre;
            pre += c;
        }
    }
}

__global__ void scatter_kernel() {
    int e = blockIdx.x * blockDim.x + threadIdx.x;
    if (e >= N_EDGES) return;
    int d = g_dst[e];
    int pos = atomicAdd(&g_off[d], 1);
    g_sdst[pos]  = d;
    g_ssrc[pos]  = g_src[e];
    g_sperm[pos] = e;
}

// ---------------------------------------------------------------------------
// Fused weight pre-split: slots 0-5 node GEMM weights, 6-7 edge weights
// ---------------------------------------------------------------------------
__global__ void wsplit_all(const float* w0, const float* w1, const float* w2,
                           const float* w3, const float* w4, const float* w5,
                           const float* we0, const float* we1) {
    int slot = blockIdx.y;
    int idx  = blockIdx.x * blockDim.x + threadIdx.x;
    if (slot < 6) {
        if (idx >= D * D) return;
        const float* W = slot == 0 ? w0 : slot == 1 ? w1 : slot == 2 ? w2
                       : slot == 3 ? w3 : slot == 4 ? w4 : w5;
        int n = idx >> 7;
        int k = idx & 127;
        float w = W[k * D + n];
        __nv_bfloat16 hi = __float2bfloat16(w);
        __nv_bfloat16 lo = __float2bfloat16(w - __bfloat162float(hi));
        uint32_t off = sw_off(n, k);
        *(__nv_bfloat16*)((char*)g_whi[slot] + off) = hi;
        *(__nv_bfloat16*)((char*)g_wlo[slot] + off) = lo;
    } else {
        if (idx >= DE * D) return;
        int l = slot - 6;
        const float* we = l == 0 ? we0 : we1;
        int n = idx & 127;
        int k = idx >> 7;
        float w = we[k * D + n];
        __nv_bfloat16 hi = __float2bfloat16(w);
        __nv_bfloat16 lo = __float2bfloat16(w - __bfloat162float(hi));
        uint32_t off = esw_off(n, k);
        *(__nv_bfloat16*)((char*)g_wehi[l] + off) = hi;
        *(__nv_bfloat16*)((char*)g_welo[l] + off) = lo;
    }
}

// ---------------------------------------------------------------------------
// Warp-autonomous HMMA edge kernel over dst-SORTED edges + run-merged atomics.
// Each warp: 16 sorted edges/tile; emb via bf16 hi/lo HMMA; tail merges
// consecutive same-dst messages in registers, one red.v4 per run.
// ---------------------------------------------------------------------------
static constexpr int EOFF_WB   = 0;            // we hi (10240) + lo (10240)
static constexpr int EOFF_AST  = 20480;        // per-warp A staging: w*2560
static constexpr int EOFF_EMB  = 40960;        // per-warp emb: w*8448
static constexpr int EMB_STRIDE = 132;
static constexpr int SMEM_EDGE = 40960 + 8 * 8448;   // 108544

__global__ void __launch_bounds__(256, 2) edge_mma(
    const float* __restrict__ X, const float* __restrict__ ea,
    const __nv_bfloat16* __restrict__ wehi, const __nv_bfloat16* __restrict__ welo,
    const float* __restrict__ be, float* __restrict__ agg)
{
    extern __shared__ char sm[];
    uint32_t smem_base = smem_to_u32(sm);
    int tid  = threadIdx.x;
    int lane = tid & 31;
    int wid  = tid >> 5;

    {
        const uint4* hg = (const uint4*)wehi;
        const uint4* lg = (const uint4*)welo;
        uint4* s = (uint4*)(sm + EOFF_WB);
        for (int i = tid; i < 640; i += 256) { s[i] = hg[i]; s[640 + i] = lg[i]; }
    }
    __syncthreads();

    uint32_t aHi = smem_base + EOFF_AST + wid * 2560;
    uint32_t aLo = aHi + 1280;
    uint32_t bHi = smem_base + EOFF_WB;
    uint32_t bLo = bHi + 10240;
    float*  embp = (float*)(sm + EOFF_EMB + wid * 8448);

    int am = lane >> 3;
    int arow = (lane & 7) + (am & 1) * 8;
    int achunkoff = am >> 1;
    int brow_loc  = ((lane >> 4) << 3) + (lane & 7);
    int bchunkoff = (lane >> 3) & 1;

    int gw     = blockIdx.x * 8 + wid;
    int nwarp  = gridDim.x * 8;
    int ntile  = N_EDGES / 16;          // 37500, exact

    for (int t = gw; t < ntile; t += nwarp) {
        int e0 = t * 16;

        // stage 16 sorted edges x 32 attrs, rows via perm; split hi/lo
        #pragma unroll
        for (int p = 0; p < 4; p++) {
            int idx = p * 32 + lane;
            int row = idx >> 3;
            int c4  = idx & 7;
            int ge  = g_sperm[e0 + row];
            float4 v = ((const float4*)ea)[(size_t)ge * 8 + c4];
            uint2 hi, lo;
            split_pack(v, hi, lo);
            uint32_t off = (uint32_t)row * 80u + (uint32_t)(c4 >> 1) * 16u
                         + (uint32_t)(c4 & 1) * 8u;
            *(uint2*)(sm + (aHi - smem_base) + off) = hi;
            *(uint2*)(sm + (aLo - smem_base) + off) = lo;
        }
        __syncwarp();

        float acc[16][4];
        #pragma unroll
        for (int nt = 0; nt < 16; nt++) {
            float2 bv = *(const float2*)(be + nt * 8 + (lane & 3) * 2);
            acc[nt][0] = bv.x; acc[nt][1] = bv.y;
            acc[nt][2] = bv.x; acc[nt][3] = bv.y;
        }

        #pragma unroll
        for (int ks = 0; ks < 2; ks++) {
            uint32_t ah[4], al[4];
            uint32_t aoff = (uint32_t)arow * 80u + (uint32_t)(ks * 2 + achunkoff) * 16u;
            ldsm4(ah, aHi + aoff);
            ldsm4(al, aLo + aoff);
            #pragma unroll
            for (int np = 0; np < 8; np++) {
                uint32_t boff = (uint32_t)(np * 16 + brow_loc) * 80u
                              + (uint32_t)(ks * 2 + bchunkoff) * 16u;
                uint32_t bh[4], bl[4];
                ldsm4(bh, bHi + boff);
                ldsm4(bl, bLo + boff);
                mma_bf16(acc[2 * np + 0], ah, bh + 0);
                mma_bf16(acc[2 * np + 1], ah, bh + 2);
                mma_bf16(acc[2 * np + 0], ah, bl + 0);
                mma_bf16(acc[2 * np + 1], ah, bl + 2);
                mma_bf16(acc[2 * np + 0], al, bh + 0);
                mma_bf16(acc[2 * np + 1], al, bh + 2);
            }
        }

        {
            int r0 = lane >> 2;
            int r1 = r0 + 8;
            int cb = (lane & 3) * 2;
            #pragma unroll
            for (int nt = 0; nt < 16; nt++) {
                *(float2*)(embp + r0 * EMB_STRIDE + nt * 8 + cb) = make_float2(acc[nt][0], acc[nt][1]);
                *(float2*)(embp + r1 * EMB_STRIDE + nt * 8 + cb) = make_float2(acc[nt][2], acc[nt][3]);
            }
        }
        __syncwarp();

        // tail: sorted dsts -> accumulate runs in registers, red.v4 per run
        float4 run = make_float4(0.f, 0.f, 0.f, 0.f);
        int cur = g_sdst[e0];                         // warp-uniform
        #pragma unroll
        for (int g = 0; g < 2; g++) {
            int base = g * 8;
            int srcs[8], dsts[8];
            #pragma unroll
            for (int i = 0; i < 8; i++) {
                dsts[i] = g_sdst[e0 + base + i];
                srcs[i] = g_ssrc[e0 + base + i];
            }
            float4 xv[8];
            #pragma unroll
            for (int i = 0; i < 8; i++)
                xv[i] = ((const float4*)X)[(size_t)srcs[i] * 32 + lane];
            #pragma unroll
            for (int i = 0; i < 8; i++) {
                float4 em = *(const float4*)(embp + (base + i) * EMB_STRIDE + lane * 4);
                if (dsts[i] != cur) {                 // warp-uniform branch
                    float* p = agg + (size_t)cur * D + lane * 4;
                    asm volatile("red.global.add.v4.f32 [%0], {%1,%2,%3,%4};"
                                 :: "l"(p), "f"(run.x), "f"(run.y), "f"(run.z), "f"(run.w) : "memory");
                    run = make_float4(0.f, 0.f, 0.f, 0.f);
                    cur = dsts[i];
                }
                run.x += fmaxf(em.x + xv[i].x, 0.f);
                run.y += fmaxf(em.y + xv[i].y, 0.f);
                run.z += fmaxf(em.z + xv[i].z, 0.f);
                run.w += fmaxf(em.w + xv[i].w, 0.f);
            }
        }
        {
            float* p = agg + (size_t)cur * D + lane * 4;
            asm volatile("red.global.add.v4.f32 [%0], {%1,%2,%3,%4};"
                         :: "l"(p), "f"(run.x), "f"(run.y), "f"(run.z), "f"(run.w) : "memory");
        }
        __syncwarp();
    }
}

// ---------------------------------------------------------------------------
// HMMA node GEMM + optional duplicate-output epilogue (folds copy_kernel)
// ---------------------------------------------------------------------------
static constexpr int OFF_AHI = 0;
static constexpr int OFF_ALO = 32768;
static constexpr int OFF_BHI = 2 * 32768;
static constexpr int OFF_BLO = 3 * 32768;
static constexpr int SMEM_MMA = 4 * 32768;   // 128 KB

template<bool RELU>
__global__ void __launch_bounds__(256) gemm_mma(
    const float* __restrict__ A,
    const __nv_bfloat16* __restrict__ Whi, const __nv_bfloat16* __restrict__ Wlo,
    const float* __restrict__ b, float* __restrict__ C, float* __restrict__ C2)
{
    extern __shared__ char sm[];
    uint32_t smem_base = smem_to_u32(sm);
    int tid  = threadIdx.x;
    int lane = tid & 31;
    int wid  = tid >> 5;

    {
        const uint4* hg = (const uint4*)Whi;
        const uint4* lg = (const uint4*)Wlo;
        uint4* hs = (uint4*)(sm + OFF_BHI);
        uint4* ls = (uint4*)(sm + OFF_BLO);
        #pragma unroll
        for (int i = 0; i < 8; i++) {
            hs[tid + i * 256] = hg[tid + i * 256];
            ls[tid + i * 256] = lg[tid + i * 256];
        }
    }

    int row0 = blockIdx.x * 128;
    #pragma unroll
    for (int i = 0; i < 16; i++) {
        int idx = tid + i * 256;
        int row = idx >> 5;
        int c4  = idx & 31;
        int rg  = row0 + row;
        if (rg >= N_NODES) rg = N_NODES - 1;
        float4 v = ((const float4*)A)[(size_t)rg * 32 + c4];
        uint2 hi, lo;
        split_pack(v, hi, lo);
        uint32_t off = sw_off(row, c4 * 4);
        *(uint2*)(sm + OFF_AHI + off) = hi;
        *(uint2*)(sm + OFF_ALO + off) = lo;
    }
    __syncthreads();

    float acc[16][4];
    #pragma unroll
    for (int nt = 0; nt < 16; nt++) {
        float2 bv = *(const float2*)(b + nt * 8 + (lane & 3) * 2);
        acc[nt][0] = bv.x; acc[nt][1] = bv.y;
        acc[nt][2] = bv.x; acc[nt][3] = bv.y;
    }

    int am = lane >> 3;
    int arow = wid * 16 + (lane & 7) + (am & 1) * 8;
    int achunkoff = am >> 1;
    int brow_loc  = ((lane >> 4) << 3) + (lane & 7);
    int bchunkoff = (lane >> 3) & 1;

    uint32_t aHi = smem_base + OFF_AHI, aLo = smem_base + OFF_ALO;
    uint32_t bHi = smem_base + OFF_BHI, bLo = smem_base + OFF_BLO;

    #pragma unroll
    for (int ks = 0; ks < 8; ks++) {
        uint32_t ah[4], al[4];
        int achunk = ks * 2 + achunkoff;
        uint32_t aoff = (uint32_t)arow * 256u + (uint32_t)((achunk ^ (arow & 7)) << 4);
        ldsm4(ah, aHi + aoff);
        ldsm4(al, aLo + aoff);
        #pragma unroll
        for (int np = 0; np < 8; np++) {
            int brow = np * 16 + brow_loc;
            int bchunk = ks * 2 + bchunkoff;
            uint32_t boff = (uint32_t)brow * 256u + (uint32_t)((bchunk ^ (brow & 7)) << 4);
            uint32_t bh[4], bl[4];
            ldsm4(bh, bHi + boff);
            ldsm4(bl, bLo + boff);
            mma_bf16(acc[2 * np + 0], ah, bh + 0);
            mma_bf16(acc[2 * np + 1], ah, bh + 2);
            mma_bf16(acc[2 * np + 0], ah, bl + 0);
            mma_bf16(acc[2 * np + 1], ah, bl + 2);
            mma_bf16(acc[2 * np + 0], al, bh + 0);
            mma_bf16(acc[2 * np + 1], al, bh + 2);
        }
    }

    int r0 = row0 + wid * 16 + (lane >> 2);
    int r1 = r0 + 8;
    int cb = (lane & 3) * 2;
    #pragma unroll
    for (int nt = 0; nt < 16; nt++) {
        float2 v0 = make_float2(acc[nt][0], acc[nt][1]);
        float2 v1 = make_float2(acc[nt][2], acc[nt][3]);
        if (RELU) {
            v0.x = fmaxf(v0.x, 0.f); v0.y = fmaxf(v0.y, 0.f);
            v1.x = fmaxf(v1.x, 0.f); v1.y = fmaxf(v1.y, 0.f);
        }
        if (r0 < N_NODES) {
            *(float2*)(C + (size_t)r0 * D + nt * 8 + cb) = v0;
            if (C2) *(float2*)(C2 + (size_t)r0 * D + nt * 8 + cb) = v0;
        }
        if (r1 < N_NODES) {
            *(float2*)(C + (size_t)r1 * D + nt * 8 + cb) = v1;
            if (C2) *(float2*)(C2 + (size_t)r1 * D + nt * 8 + cb) = v1;
        }
    }
}

// ---------------------------------------------------------------------------
static bool g_attr_done = false;

extern "C" void kernel_launch(void* const* d_in, const int* in_sizes, int n_in,
                              void* d_out, int out_size)
{
    const float* x     = (const float*)d_in[0];
    const void*  eidx  =               d_in[1];
    const float* ea    = (const float*)d_in[2];
    const float* w1_0  = (const float*)d_in[3];
    const float* b1_0  = (const float*)d_in[4];
    const float* w2_0  = (const float*)d_in[5];
    const float* b2_0  = (const float*)d_in[6];
    const float* we_0  = (const float*)d_in[7];
    const float* be_0  = (const float*)d_in[8];
    const float* w1_1  = (const float*)d_in[9];
    const float* b1_1  = (const float*)d_in[10];
    const float* w2_1  = (const float*)d_in[11];
    const float* b2_1  = (const float*)d_in[12];
    const float* we_1  = (const float*)d_in[13];
    const float* be_1  = (const float*)d_in[14];
    const float* fc1_w = (const float*)d_in[15];
    const float* fc1_b = (const float*)d_in[16];
    const float* fc2_w = (const float*)d_in[17];
    const float* fc2_b = (const float*)d_in[18];
    float* out = (float*)d_out;

    float *bufA, *bufB, *bufC;
    __nv_bfloat16 *whi, *wlo, *wehi, *welo;
    int *cnt;
    cudaGetSymbolAddress((void**)&bufA, g_bufA);
    cudaGetSymbolAddress((void**)&bufB, g_bufB);
    cudaGetSymbolAddress((void**)&bufC, g_bufC);
    cudaGetSymbolAddress((void**)&whi,  g_whi);
    cudaGetSymbolAddress((void**)&wlo,  g_wlo);
    cudaGetSymbolAddress((void**)&wehi, g_wehi);
    cudaGetSymbolAddress((void**)&welo, g_welo);
    cudaGetSymbolAddress((void**)&cnt,  g_cnt);

    if (!g_attr_done) {
        cudaFuncSetAttribute((const void*)gemm_mma<true>,
                             cudaFuncAttributeMaxDynamicSharedMemorySize, SMEM_MMA);
        cudaFuncSetAttribute((const void*)gemm_mma<false>,
                             cudaFuncAttributeMaxDynamicSharedMemorySize, SMEM_MMA);
        cudaFuncSetAttribute((const void*)edge_mma,
                             cudaFuncAttributeMaxDynamicSharedMemorySize, SMEM_EDGE);
        g_attr_done = true;
    }

    int n_words = in_sizes[1];
    detect_kernel<<<1, 32>>>((const int*)eidx, n_words);
    convert_kernel<<<(N_EDGES + 255) / 256, 256>>>(eidx);

    // dst counting sort (once; reused by both edge layers)
    zero_kernel<<<(N_NODES + 256) / 256, 256>>>(cnt, N_NODES + 1);
    hist_kernel<<<(N_EDGES + 255) / 256, 256>>>();
    scan_kernel<<<1, 1024>>>();
    scatter_kernel<<<(N_EDGES + 255) / 256, 256>>>();

    // fused weight pre-split (1 launch for all 8 weights)
    {
        dim3 grid(64, 8);
        wsplit_all<<<grid, 256>>>(w1_0, w2_0, w1_1, w2_1, fc1_w, fc2_w, we_0, we_1);
    }

    int n4 = N_NODES * D / 4;
    int gt = (N_NODES + 127) / 128;   // 391 M-tiles
    int ge = 296;                     // 2 CTA/SM x 148 SMs, persistent

    // ----- layer 0 -----
    copy_kernel<<<(n4 + 255) / 256, 256>>>((const float4*)x, (float4*)bufA, n4);
    edge_mma<<<ge, 256, SMEM_EDGE>>>(x, ea, wehi + 0 * 5120, welo + 0 * 5120, be_0, bufA);
    gemm_mma<true ><<<gt, 256, SMEM_MMA>>>(bufA, whi + 0 * D * D, wlo + 0 * D * D, b1_0, bufB, nullptr);
    gemm_mma<true ><<<gt, 256, SMEM_MMA>>>(bufB, whi + 1 * D * D, wlo + 1 * D * D, b2_0, bufC, bufA);

    // ----- layer 1 -----
    edge_mma<<<ge, 256, SMEM_EDGE>>>(bufC, ea, wehi + 1 * 5120, welo + 1 * 5120, be_1, bufA);
    gemm_mma<true ><<<gt, 256, SMEM_MMA>>>(bufA, whi + 2 * D * D, wlo + 2 * D * D, b1_1, bufB, nullptr);
    gemm_mma<true ><<<gt, 256, SMEM_MMA>>>(bufB, whi + 3 * D * D, wlo + 3 * D * D, b2_1, bufC, nullptr);

    // ----- head -----
    gemm_mma<true ><<<gt, 256, SMEM_MMA>>>(bufC, whi + 4 * D * D, wlo + 4 * D * D, fc1_b, bufB, nullptr);
    gemm_mma<false><<<gt, 256, SMEM_MMA>>>(bufB, whi + 5 * D * D, wlo + 5 * D * D, fc2_b, out, nullptr);
}

// round 15
// speedup vs baseline: 1.2191x; 1.2191x over previous
#include <cuda_runtime.h>
#include <cuda_bf16.h>
#include <cstdint>

#define N_NODES 50000
#define N_EDGES 600000
#define D 128
#define DE 32

// ---------------------------------------------------------------------------
// Scratch (static device globals — no runtime allocation allowed)
// ---------------------------------------------------------------------------
__device__ int   g_src[N_EDGES];
__device__ int   g_dst[N_EDGES];
__device__ float g_bufA[N_NODES * D];
__device__ float g_bufB[N_NODES * D];
__device__ float g_bufC[N_NODES * D];
__device__ int   g_is64;
// node-GEMM weights: [6][128x128 bf16] in B-operand layout (stride 256B, XOR swizzle)
__device__ __nv_bfloat16 g_whi[6][D * D];
__device__ __nv_bfloat16 g_wlo[6][D * D];
// edge weights: [2 layers][128 n-rows x 80B stride] hi/lo planes (5120 bf16 each)
__device__ __nv_bfloat16 g_wehi[2][5120];
__device__ __nv_bfloat16 g_welo[2][5120];

// ---------------------------------------------------------------------------
// helpers
// ---------------------------------------------------------------------------
__device__ __forceinline__ uint32_t smem_to_u32(const void* p) {
    uint32_t a;
    asm("{ .reg .u64 t; cvta.to.shared.u64 t, %1; cvt.u32.u64 %0, t; }" : "=r"(a) : "l"(p));
    return a;
}

__device__ __host__ __forceinline__ uint32_t sw_off(int row, int col) {
    return (uint32_t)row * 256u + (uint32_t)(((col >> 3) ^ (row & 7)) << 4)
         + (uint32_t)(col & 7) * 2u;
}
__device__ __host__ __forceinline__ uint32_t esw_off(int row, int col) {
    return (uint32_t)row * 80u + (uint32_t)((col >> 3) << 4) + (uint32_t)(col & 7) * 2u;
}

__device__ __forceinline__ void ldsm4(uint32_t* r, uint32_t addr) {
    asm volatile("ldmatrix.sync.aligned.m8n8.x4.shared.b16 {%0,%1,%2,%3}, [%4];"
                 : "=r"(r[0]), "=r"(r[1]), "=r"(r[2]), "=r"(r[3]) : "r"(addr));
}

__device__ __forceinline__ void mma_bf16(float* d, const uint32_t* a, const uint32_t* b) {
    asm volatile("mma.sync.aligned.m16n8k16.row.col.f32.bf16.bf16.f32 "
                 "{%0,%1,%2,%3}, {%4,%5,%6,%7}, {%8,%9}, {%0,%1,%2,%3};"
                 : "+f"(d[0]), "+f"(d[1]), "+f"(d[2]), "+f"(d[3])
                 : "r"(a[0]), "r"(a[1]), "r"(a[2]), "r"(a[3]), "r"(b[0]), "r"(b[1]));
}

__device__ __forceinline__ void split_pack(float4 v, uint2& hi, uint2& lo) {
    __nv_bfloat16 hx = __float2bfloat16(v.x), hy = __float2bfloat16(v.y);
    __nv_bfloat16 hz = __float2bfloat16(v.z), hw = __float2bfloat16(v.w);
    __nv_bfloat16 lx = __float2bfloat16(v.x - __bfloat162float(hx));
    __nv_bfloat16 ly = __float2bfloat16(v.y - __bfloat162float(hy));
    __nv_bfloat16 lz = __float2bfloat16(v.z - __bfloat162float(hz));
    __nv_bfloat16 lw = __float2bfloat16(v.w - __bfloat162float(hw));
    hi.x = ((uint32_t)__bfloat16_as_ushort(hy) << 16) | __bfloat16_as_ushort(hx);
    hi.y = ((uint32_t)__bfloat16_as_ushort(hw) << 16) | __bfloat16_as_ushort(hz);
    lo.x = ((uint32_t)__bfloat16_as_ushort(ly) << 16) | __bfloat16_as_ushort(lx);
    lo.y = ((uint32_t)__bfloat16_as_ushort(lw) << 16) | __bfloat16_as_ushort(lz);
}

__device__ __forceinline__ uint32_t pack_bf16x2(float a, float b) {
    __nv_bfloat16 x = __float2bfloat16(a), y = __float2bfloat16(b);
    return ((uint32_t)__bfloat16_as_ushort(y) << 16) | __bfloat16_as_ushort(x);
}
__device__ __forceinline__ uint32_t pack_bf16x2_lo(float a, float b, uint32_t hipacked) {
    float ax = __bfloat162float(__ushort_as_bfloat16((unsigned short)(hipacked & 0xFFFF)));
    float ay = __bfloat162float(__ushort_as_bfloat16((unsigned short)(hipacked >> 16)));
    __nv_bfloat16 x = __float2bfloat16(a - ax), y = __float2bfloat16(b - ay);
    return ((uint32_t)__bfloat16_as_ushort(y) << 16) | __bfloat16_as_ushort(x);
}

// ---------------------------------------------------------------------------
// edge_index dtype detection / conversion / copy / dummy (profile aligner)
// ---------------------------------------------------------------------------
__global__ void detect_kernel(const int* __restrict__ p, int n_words) {
    if (threadIdx.x == 0 && blockIdx.x == 0) {
        int all0 = 1;
        int lim = n_words / 2 < 64 ? n_words / 2 : 64;
        for (int i = 0; i < lim; i++) {
            if (p[2 * i + 1] != 0) { all0 = 0; break; }
        }
        g_is64 = all0;
    }
}

__global__ void convert_kernel(const void* __restrict__ eidx) {
    int e = blockIdx.x * blockDim.x + threadIdx.x;
    if (e >= N_EDGES) return;
    if (g_is64) {
        const long long* p = (const long long*)eidx;
        g_src[e] = (int)p[e];
        g_dst[e] = (int)p[N_EDGES + e];
    } else {
        const int* p = (const int*)eidx;
        g_src[e] = p[e];
        g_dst[e] = p[N_EDGES + e];
    }
}

__global__ void copy_kernel(const float4* __restrict__ src, float4* __restrict__ dst, int n4) {
    int i = blockIdx.x * blockDim.x + threadIdx.x;
    if (i < n4) dst[i] = src[i];
}

__global__ void dummy_kernel() {}

// ---------------------------------------------------------------------------
// Fused weight pre-split: slots 0-5 node GEMM weights, 6-7 edge weights
// ---------------------------------------------------------------------------
__global__ void wsplit_all(const float* w0, const float* w1, const float* w2,
                           const float* w3, const float* w4, const float* w5,
                           const float* we0, const float* we1) {
    int slot = blockIdx.y;
    int idx  = blockIdx.x * blockDim.x + threadIdx.x;
    if (slot < 6) {
        if (idx >= D * D) return;
        const float* W = slot == 0 ? w0 : slot == 1 ? w1 : slot == 2 ? w2
                       : slot == 3 ? w3 : slot == 4 ? w4 : w5;
        int n = idx >> 7;
        int k = idx & 127;
        float w = W[k * D + n];
        __nv_bfloat16 hi = __float2bfloat16(w);
        __nv_bfloat16 lo = __float2bfloat16(w - __bfloat162float(hi));
        uint32_t off = sw_off(n, k);
        *(__nv_bfloat16*)((char*)g_whi[slot] + off) = hi;
        *(__nv_bfloat16*)((char*)g_wlo[slot] + off) = lo;
    } else {
        if (idx >= DE * D) return;
        int l = slot - 6;
        const float* we = l == 0 ? we0 : we1;
        int n = idx & 127;
        int k = idx >> 7;
        float w = we[k * D + n];
        __nv_bfloat16 hi = __float2bfloat16(w);
        __nv_bfloat16 lo = __float2bfloat16(w - __bfloat162float(hi));
        uint32_t off = esw_off(n, k);
        *(__nv_bfloat16*)((char*)g_wehi[l] + off) = hi;
        *(__nv_bfloat16*)((char*)g_welo[l] + off) = lo;
    }
}

// ---------------------------------------------------------------------------
// Warp-autonomous HMMA edge kernel (R11 winner, unsorted edges)
// ---------------------------------------------------------------------------
static constexpr int EOFF_WB   = 0;
static constexpr int EOFF_AST  = 20480;
static constexpr int EOFF_EMB  = 40960;
static constexpr int EMB_STRIDE = 132;
static constexpr int SMEM_EDGE = 40960 + 8 * 8448;   // 108544

__global__ void __launch_bounds__(256, 2) edge_mma(
    const float* __restrict__ X, const float* __restrict__ ea,
    const __nv_bfloat16* __restrict__ wehi, const __nv_bfloat16* __restrict__ welo,
    const float* __restrict__ be, float* __restrict__ agg)
{
    extern __shared__ char sm[];
    uint32_t smem_base = smem_to_u32(sm);
    int tid  = threadIdx.x;
    int lane = tid & 31;
    int wid  = tid >> 5;

    {
        const uint4* hg = (const uint4*)wehi;
        const uint4* lg = (const uint4*)welo;
        uint4* s = (uint4*)(sm + EOFF_WB);
        for (int i = tid; i < 640; i += 256) { s[i] = hg[i]; s[640 + i] = lg[i]; }
    }
    __syncthreads();

    uint32_t aHi = smem_base + EOFF_AST + wid * 2560;
    uint32_t aLo = aHi + 1280;
    uint32_t bHi = smem_base + EOFF_WB;
    uint32_t bLo = bHi + 10240;
    float*  embp = (float*)(sm + EOFF_EMB + wid * 8448);

    int am = lane >> 3;
    int arow = (lane & 7) + (am & 1) * 8;
    int achunkoff = am >> 1;
    int brow_loc  = ((lane >> 4) << 3) + (lane & 7);
    int bchunkoff = (lane >> 3) & 1;

    int gw     = blockIdx.x * 8 + wid;
    int nwarp  = gridDim.x * 8;
    int ntile  = N_EDGES / 16;

    for (int t = gw; t < ntile; t += nwarp) {
        int e0 = t * 16;

        #pragma unroll
        for (int p = 0; p < 4; p++) {
            int idx = p * 32 + lane;
            int row = idx >> 3;
            int c4  = idx & 7;
            float4 v = ((const float4*)ea)[(size_t)(e0 + row) * 8 + c4];
            uint2 hi, lo;
            split_pack(v, hi, lo);
            uint32_t off = (uint32_t)row * 80u + (uint32_t)(c4 >> 1) * 16u
                         + (uint32_t)(c4 & 1) * 8u;
            *(uint2*)(sm + (aHi - smem_base) + off) = hi;
            *(uint2*)(sm + (aLo - smem_base) + off) = lo;
        }
        __syncwarp();

        float acc[16][4];
        #pragma unroll
        for (int nt = 0; nt < 16; nt++) {
            float2 bv = *(const float2*)(be + nt * 8 + (lane & 3) * 2);
            acc[nt][0] = bv.x; acc[nt][1] = bv.y;
            acc[nt][2] = bv.x; acc[nt][3] = bv.y;
        }

        #pragma unroll
        for (int ks = 0; ks < 2; ks++) {
            uint32_t ah[4], al[4];
            uint32_t aoff = (uint32_t)arow * 80u + (uint32_t)(ks * 2 + achunkoff) * 16u;
            ldsm4(ah, aHi + aoff);
            ldsm4(al, aLo + aoff);
            #pragma unroll
            for (int np = 0; np < 8; np++) {
                uint32_t boff = (uint32_t)(np * 16 + brow_loc) * 80u
                              + (uint32_t)(ks * 2 + bchunkoff) * 16u;
                uint32_t bh[4], bl[4];
                ldsm4(bh, bHi + boff);
                ldsm4(bl, bLo + boff);
                mma_bf16(acc[2 * np + 0], ah, bh + 0);
                mma_bf16(acc[2 * np + 1], ah, bh + 2);
                mma_bf16(acc[2 * np + 0], ah, bl + 0);
                mma_bf16(acc[2 * np + 1], ah, bl + 2);
                mma_bf16(acc[2 * np + 0], al, bh + 0);
                mma_bf16(acc[2 * np + 1], al, bh + 2);
            }
        }

        {
            int r0 = lane >> 2;
            int r1 = r0 + 8;
            int cb = (lane & 3) * 2;
            #pragma unroll
            for (int nt = 0; nt < 16; nt++) {
                *(float2*)(embp + r0 * EMB_STRIDE + nt * 8 + cb) = make_float2(acc[nt][0], acc[nt][1]);
                *(float2*)(embp + r1 * EMB_STRIDE + nt * 8 + cb) = make_float2(acc[nt][2], acc[nt][3]);
            }
        }
        __syncwarp();

        #pragma unroll
        for (int g = 0; g < 2; g++) {
            int base = g * 8;
            int srcs[8], dsts[8];
            #pragma unroll
            for (int i = 0; i < 8; i++) {
                srcs[i] = g_src[e0 + base + i];
                dsts[i] = g_dst[e0 + base + i];
            }
            float4 xv[8];
            #pragma unroll
            for (int i = 0; i < 8; i++)
                xv[i] = ((const float4*)X)[(size_t)srcs[i] * 32 + lane];
            #pragma unroll
            for (int i = 0; i < 8; i++) {
                float4 em = *(const float4*)(embp + (base + i) * EMB_STRIDE + lane * 4);
                float mx = fmaxf(em.x + xv[i].x, 0.f);
                float my = fmaxf(em.y + xv[i].y, 0.f);
                float mz = fmaxf(em.z + xv[i].z, 0.f);
                float mw = fmaxf(em.w + xv[i].w, 0.f);
                float* p = agg + (size_t)dsts[i] * D + lane * 4;
                asm volatile("red.global.add.v4.f32 [%0], {%1,%2,%3,%4};"
                             :: "l"(p), "f"(mx), "f"(my), "f"(mz), "f"(mw) : "memory");
            }
        }
        __syncwarp();
    }
}

// ---------------------------------------------------------------------------
// FUSED double GEMM: C = act2( relu(A@W1+b1) @ W2 + b2 )
// One kernel per GEMM pair -> saves a full 51MB activation round-trip.
// smem: A hi/lo (64KB) + B1 hi/lo (64KB) + B2 hi/lo (64KB) = 192KB, 1 CTA/SM.
// A rows are warp-private: after phase-1 each warp re-splits its own 16 rows
// of h1 into its A-plane slice (only __syncwarp needed).
// ---------------------------------------------------------------------------
static constexpr int F_AHI  = 0;
static constexpr int F_ALO  = 32768;
static constexpr int F_B1HI = 65536;
static constexpr int F_B1LO = 98304;
static constexpr int F_B2HI = 131072;
static constexpr int F_B2LO = 163840;
static constexpr int SMEM_F = 196608;   // 192 KB

template<bool RELU2>
__global__ void __launch_bounds__(256) gemm2_mma(
    const float* __restrict__ A,
    const __nv_bfloat16* __restrict__ W1hi, const __nv_bfloat16* __restrict__ W1lo,
    const float* __restrict__ b1,
    const __nv_bfloat16* __restrict__ W2hi, const __nv_bfloat16* __restrict__ W2lo,
    const float* __restrict__ b2,
    float* __restrict__ C, float* __restrict__ C2)
{
    extern __shared__ char sm[];
    uint32_t smem_base = smem_to_u32(sm);
    int tid  = threadIdx.x;
    int lane = tid & 31;
    int wid  = tid >> 5;

    // stage both B pairs (pre-split + pre-swizzled): linear uint4 copies
    {
        const uint4* h1 = (const uint4*)W1hi;
        const uint4* l1 = (const uint4*)W1lo;
        const uint4* h2 = (const uint4*)W2hi;
        const uint4* l2 = (const uint4*)W2lo;
        uint4* s1h = (uint4*)(sm + F_B1HI);
        uint4* s1l = (uint4*)(sm + F_B1LO);
        uint4* s2h = (uint4*)(sm + F_B2HI);
        uint4* s2l = (uint4*)(sm + F_B2LO);
        #pragma unroll
        for (int i = 0; i < 8; i++) {
            s1h[tid + i * 256] = h1[tid + i * 256];
            s1l[tid + i * 256] = l1[tid + i * 256];
            s2h[tid + i * 256] = h2[tid + i * 256];
            s2l[tid + i * 256] = l2[tid + i * 256];
        }
    }

    // stage A: load fp32, split hi/lo, store swizzled
    int row0 = blockIdx.x * 128;
    #pragma unroll
    for (int i = 0; i < 16; i++) {
        int idx = tid + i * 256;
        int row = idx >> 5;
        int c4  = idx & 31;
        int rg  = row0 + row;
        if (rg >= N_NODES) rg = N_NODES - 1;
        float4 v = ((const float4*)A)[(size_t)rg * 32 + c4];
        uint2 hi, lo;
        split_pack(v, hi, lo);
        uint32_t off = sw_off(row, c4 * 4);
        *(uint2*)(sm + F_AHI + off) = hi;
        *(uint2*)(sm + F_ALO + off) = lo;
    }
    __syncthreads();

    int am = lane >> 3;
    int arow = wid * 16 + (lane & 7) + (am & 1) * 8;
    int achunkoff = am >> 1;
    int brow_loc  = ((lane >> 4) << 3) + (lane & 7);
    int bchunkoff = (lane >> 3) & 1;

    uint32_t aHi = smem_base + F_AHI, aLo = smem_base + F_ALO;

    float acc[16][4];

    // ---------------- phase 1: h1 = relu(A@W1 + b1) ----------------
    #pragma unroll
    for (int nt = 0; nt < 16; nt++) {
        float2 bv = *(const float2*)(b1 + nt * 8 + (lane & 3) * 2);
        acc[nt][0] = bv.x; acc[nt][1] = bv.y;
        acc[nt][2] = bv.x; acc[nt][3] = bv.y;
    }
    {
        uint32_t bHi = smem_base + F_B1HI, bLo = smem_base + F_B1LO;
        #pragma unroll
        for (int ks = 0; ks < 8; ks++) {
            uint32_t ah[4], al[4];
            int achunk = ks * 2 + achunkoff;
            uint32_t aoff = (uint32_t)arow * 256u + (uint32_t)((achunk ^ (arow & 7)) << 4);
            ldsm4(ah, aHi + aoff);
            ldsm4(al, aLo + aoff);
            #pragma unroll
            for (int np = 0; np < 8; np++) {
                int brow = np * 16 + brow_loc;
                int bchunk = ks * 2 + bchunkoff;
                uint32_t boff = (uint32_t)brow * 256u + (uint32_t)((bchunk ^ (brow & 7)) << 4);
                uint32_t bh[4], bl[4];
                ldsm4(bh, bHi + boff);
                ldsm4(bl, bLo + boff);
                mma_bf16(acc[2 * np + 0], ah, bh + 0);
                mma_bf16(acc[2 * np + 1], ah, bh + 2);
                mma_bf16(acc[2 * np + 0], ah, bl + 0);
                mma_bf16(acc[2 * np + 1], ah, bl + 2);
                mma_bf16(acc[2 * np + 0], al, bh + 0);
                mma_bf16(acc[2 * np + 1], al, bh + 2);
            }
        }
    }

    // relu + re-split h1 into this warp's own A-plane rows (warp-private)
    __syncwarp();   // all lanes done reading A rows before overwrite
    {
        int r0 = wid * 16 + (lane >> 2);
        int r1 = r0 + 8;
        int cb = (lane & 3) * 2;
        #pragma unroll
        for (int nt = 0; nt < 16; nt++) {
            float v00 = fmaxf(acc[nt][0], 0.f), v01 = fmaxf(acc[nt][1], 0.f);
            float v10 = fmaxf(acc[nt][2], 0.f), v11 = fmaxf(acc[nt][3], 0.f);
            int col = nt * 8 + cb;
            uint32_t o0 = sw_off(r0, col);
            uint32_t o1 = sw_off(r1, col);
            uint32_t h0 = pack_bf16x2(v00, v01);
            uint32_t h1 = pack_bf16x2(v10, v11);
            *(uint32_t*)(sm + F_AHI + o0) = h0;
            *(uint32_t*)(sm + F_AHI + o1) = h1;
            *(uint32_t*)(sm + F_ALO + o0) = pack_bf16x2_lo(v00, v01, h0);
            *(uint32_t*)(sm + F_ALO + o1) = pack_bf16x2_lo(v10, v11, h1);
        }
    }
    __syncwarp();

    // ---------------- phase 2: C = act2(h1@W2 + b2) ----------------
    #pragma unroll
    for (int nt = 0; nt < 16; nt++) {
        float2 bv = *(const float2*)(b2 + nt * 8 + (lane & 3) * 2);
        acc[nt][0] = bv.x; acc[nt][1] = bv.y;
        acc[nt][2] = bv.x; acc[nt][3] = bv.y;
    }
    {
        uint32_t bHi = smem_base + F_B2HI, bLo = smem_base + F_B2LO;
        #pragma unroll
        for (int ks = 0; ks < 8; ks++) {
            uint32_t ah[4], al[4];
            int achunk = ks * 2 + achunkoff;
            uint32_t aoff = (uint32_t)arow * 256u + (uint32_t)((achunk ^ (arow & 7)) << 4);
            ldsm4(ah, aHi + aoff);
            ldsm4(al, aLo + aoff);
            #pragma unroll
            for (int np = 0; np < 8; np++) {
                int brow = np * 16 + brow_loc;
                int bchunk = ks * 2 + bchunkoff;
                uint32_t boff = (uint32_t)brow * 256u + (uint32_t)((bchunk ^ (brow & 7)) << 4);
                uint32_t bh[4], bl[4];
                ldsm4(bh, bHi + boff);
                ldsm4(bl, bLo + boff);
                mma_bf16(acc[2 * np + 0], ah, bh + 0);
                mma_bf16(acc[2 * np + 1], ah, bh + 2);
                mma_bf16(acc[2 * np + 0], ah, bl + 0);
                mma_bf16(acc[2 * np + 1], ah, bl + 2);
                mma_bf16(acc[2 * np + 0], al, bh + 0);
                mma_bf16(acc[2 * np + 1], al, bh + 2);
            }
        }
    }

    int r0 = row0 + wid * 16 + (lane >> 2);
    int r1 = r0 + 8;
    int cb = (lane & 3) * 2;
    #pragma unroll
    for (int nt = 0; nt < 16; nt++) {
        float2 v0 = make_float2(acc[nt][0], acc[nt][1]);
        float2 v1 = make_float2(acc[nt][2], acc[nt][3]);
        if (RELU2) {
            v0.x = fmaxf(v0.x, 0.f); v0.y = fmaxf(v0.y, 0.f);
            v1.x = fmaxf(v1.x, 0.f); v1.y = fmaxf(v1.y, 0.f);
        }
        if (r0 < N_NODES) {
            *(float2*)(C + (size_t)r0 * D + nt * 8 + cb) = v0;
            if (C2) *(float2*)(C2 + (size_t)r0 * D + nt * 8 + cb) = v0;
        }
        if (r1 < N_NODES) {
            *(float2*)(C + (size_t)r1 * D + nt * 8 + cb) = v1;
            if (C2) *(float2*)(C2 + (size_t)r1 * D + nt * 8 + cb) = v1;
        }
    }
}

// ---------------------------------------------------------------------------
static bool g_attr_done = false;

extern "C" void kernel_launch(void* const* d_in, const int* in_sizes, int n_in,
                              void* d_out, int out_size)
{
    const float* x     = (const float*)d_in[0];
    const void*  eidx  =               d_in[1];
    const float* ea    = (const float*)d_in[2];
    const float* w1_0  = (const float*)d_in[3];
    const float* b1_0  = (const float*)d_in[4];
    const float* w2_0  = (const float*)d_in[5];
    const float* b2_0  = (const float*)d_in[6];
    const float* we_0  = (const float*)d_in[7];
    const float* be_0  = (const float*)d_in[8];
    const float* w1_1  = (const float*)d_in[9];
    const float* b1_1  = (const float*)d_in[10];
    const float* w2_1  = (const float*)d_in[11];
    const float* b2_1  = (const float*)d_in[12];
    const float* we_1  = (const float*)d_in[13];
    const float* be_1  = (const float*)d_in[14];
    const float* fc1_w = (const float*)d_in[15];
    const float* fc1_b = (const float*)d_in[16];
    const float* fc2_w = (const float*)d_in[17];
    const float* fc2_b = (const float*)d_in[18];
    float* out = (float*)d_out;

    float *bufA, *bufB, *bufC;
    __nv_bfloat16 *whi, *wlo, *wehi, *welo;
    cudaGetSymbolAddress((void**)&bufA, g_bufA);
    cudaGetSymbolAddress((void**)&bufB, g_bufB);
    cudaGetSymbolAddress((void**)&bufC, g_bufC);
    cudaGetSymbolAddress((void**)&whi,  g_whi);
    cudaGetSymbolAddress((void**)&wlo,  g_wlo);
    cudaGetSymbolAddress((void**)&wehi, g_wehi);
    cudaGetSymbolAddress((void**)&welo, g_welo);

    if (!g_attr_done) {
        cudaFuncSetAttribute((const void*)gemm2_mma<true>,
                             cudaFuncAttributeMaxDynamicSharedMemorySize, SMEM_F);
        cudaFuncSetAttribute((const void*)gemm2_mma<false>,
                             cudaFuncAttributeMaxDynamicSharedMemorySize, SMEM_F);
        cudaFuncSetAttribute((const void*)edge_mma,
                             cudaFuncAttributeMaxDynamicSharedMemorySize, SMEM_EDGE);
        g_attr_done = true;
    }

    int n_words = in_sizes[1];
    int n4 = N_NODES * D / 4;
    int gt = (N_NODES + 127) / 128;   // 391 M-tiles
    int ge = 296;                     // 2 CTA/SM x 148 SMs

    // launches 1-5 (so edge_mma is launch #6 for ncu -s 5 -c 1)
    detect_kernel<<<1, 32>>>((const int*)eidx, n_words);                       // 1
    convert_kernel<<<(N_EDGES + 255) / 256, 256>>>(eidx);                      // 2
    {
        dim3 grid(64, 8);
        wsplit_all<<<grid, 256>>>(w1_0, w2_0, w1_1, w2_1, fc1_w, fc2_w, we_0, we_1);  // 3
    }
    copy_kernel<<<(n4 + 255) / 256, 256>>>((const float4*)x, (float4*)bufA, n4);      // 4
    dummy_kernel<<<1, 32>>>();                                                 // 5

    // ----- layer 0 -----
    edge_mma<<<ge, 256, SMEM_EDGE>>>(x, ea, wehi + 0 * 5120, welo + 0 * 5120, be_0, bufA);   // 6
    gemm2_mma<true ><<<gt, 256, SMEM_F>>>(bufA,
        whi + 0 * D * D, wlo + 0 * D * D, b1_0,
        whi + 1 * D * D, wlo + 1 * D * D, b2_0, bufC, bufA);

    // ----- layer 1 -----
    edge_mma<<<ge, 256, SMEM_EDGE>>>(bufC, ea, wehi + 1 * 5120, welo + 1 * 5120, be_1, bufA);
    gemm2_mma<true ><<<gt, 256, SMEM_F>>>(bufA,
        whi + 2 * D * D, wlo + 2 * D * D, b1_1,
        whi + 3 * D * D, wlo + 3 * D * D, b2_1, bufC, nullptr);

    // ----- head (fc1 + fc2 fused) -----
    gemm2_mma<false><<<gt, 256, SMEM_F>>>(bufC,
        whi + 4 * D * D, wlo + 4 * D * D, fc1_b,
        whi + 5 * D * D, wlo + 5 * D * D, fc2_b, out, nullptr);
}